// round 4
// baseline (speedup 1.0000x reference)
#include <cuda_runtime.h>
#include <cstdint>

// VQ codebook lookup, numerics-matched to the jax reference:
//   dist[n,q] = fl( fl(x_sq[n] - fl(2*xw[n,q])) + w_sq[q] ),  argmin_q (ties -> lowest q)
//   out = gathered codebook rows (N*E fp32) [+ idx as float (N)]
//
// x_sq / w_sq use STRICTLY SEQUENTIAL fp32 accumulation (separate mul/add
// roundings) to mirror the reference reduction. xw is a tiled fp32 GEMM with
// sequential-k single-accumulator FMA.

#define E_DIM 512
#define TM 64
#define TQ 128
#define KC 16
#define THREADS 256
#define Q_MAX 8192
#define N_MAX 16384

__device__ float g_wsq[Q_MAX];   // ||w_q||^2  (sequential fp32 sum)
__device__ float g_xsq[N_MAX];   // ||x_n||^2  (sequential fp32 sum)

// ---------------------------------------------------------------------------
// Sequential row sum-of-squares: one thread per row, order e = 0..E-1,
// s = fl(s + fl(v*v)).  Coalesced via 64-column smem tiles.
// which = 0 -> g_xsq, 1 -> g_wsq.
// ---------------------------------------------------------------------------
__global__ __launch_bounds__(128) void rowsq_kernel(const float* __restrict__ a,
                                                    int nrows, int which)
{
    __shared__ float tile[128][65];
    const int t = threadIdx.x;
    const int r0 = blockIdx.x * 128;
    float s = 0.f;
    for (int c0 = 0; c0 < E_DIM; c0 += 64) {
#pragma unroll
        for (int i = 0; i < 64; i++) {
            int lin = i * 128 + t;
            int c = lin & 63;
            int r = lin >> 6;
            tile[r][c] = a[(size_t)(r0 + r) * E_DIM + c0 + c];
        }
        __syncthreads();
#pragma unroll
        for (int c = 0; c < 64; c++) {
            float v = tile[t][c];
            s = __fadd_rn(s, __fmul_rn(v, v));   // strictly sequential, no FMA
        }
        __syncthreads();
    }
    if (r0 + t < nrows) {
        if (which == 0) g_xsq[r0 + t] = s;
        else            g_wsq[r0 + t] = s;
    }
}

// ---------------------------------------------------------------------------
// Fused GEMM + reference-rounded argmin + gather
// ---------------------------------------------------------------------------
__global__ __launch_bounds__(THREADS) void vq_kernel(
    const float* __restrict__ x, const float* __restrict__ w,
    float* __restrict__ out, float* __restrict__ out_idx,
    int N, int Q, int write_idx)
{
    __shared__ __align__(16) float sx[KC][TM + 4];
    __shared__ __align__(16) float sw[KC][TQ + 4];
    __shared__ float bestS[TM][17];
    __shared__ int   idxS[TM][17];
    __shared__ int   finalIdx[TM];

    const int t  = threadIdx.x;
    const int tx = t & 15;          // 16 threads across TQ (8 codes each)
    const int ty = t >> 4;          // 16 threads across TM (4 rows each)
    const int n0 = blockIdx.x * TM;

    float xsq[4];
#pragma unroll
    for (int i = 0; i < 4; i++) xsq[i] = g_xsq[n0 + ty * 4 + i];

    float best[4];
    int   bidx[4];
#pragma unroll
    for (int i = 0; i < 4; i++) { best[i] = 3.4e38f; bidx[i] = 0x7fffffff; }

    for (int q0 = 0; q0 < Q; q0 += TQ) {
        float acc[4][8];
#pragma unroll
        for (int i = 0; i < 4; i++)
#pragma unroll
            for (int j = 0; j < 8; j++) acc[i][j] = 0.f;

        for (int kb = 0; kb < E_DIM; kb += KC) {
#pragma unroll
            for (int i = 0; i < (TM * KC) / THREADS; i++) {
                int gid = t + i * THREADS;
                int k = gid & (KC - 1);
                int r = gid >> 4;
                sx[k][r] = x[(size_t)(n0 + r) * E_DIM + kb + k];
            }
#pragma unroll
            for (int i = 0; i < (TQ * KC) / THREADS; i++) {
                int gid = t + i * THREADS;
                int k = gid & (KC - 1);
                int q = gid >> 4;
                sw[k][q] = w[(size_t)(q0 + q) * E_DIM + kb + k];
            }
            __syncthreads();

#pragma unroll
            for (int kk = 0; kk < KC; kk++) {
                float4 a  = *(const float4*)&sx[kk][ty * 4];
                float4 b0 = *(const float4*)&sw[kk][tx * 8];
                float4 b1 = *(const float4*)&sw[kk][tx * 8 + 4];
                float av[4] = {a.x, a.y, a.z, a.w};
                float bv[8] = {b0.x, b0.y, b0.z, b0.w, b1.x, b1.y, b1.z, b1.w};
#pragma unroll
                for (int i = 0; i < 4; i++)
#pragma unroll
                    for (int j = 0; j < 8; j++)
                        acc[i][j] = __fmaf_rn(av[i], bv[j], acc[i][j]);
            }
            __syncthreads();
        }

        // Reference-matched distance rounding + running argmin.
        // q ascends with j (inner) and q0 (outer); strict '<' keeps lowest q on ties.
#pragma unroll
        for (int j = 0; j < 8; j++) {
            int q = q0 + tx * 8 + j;
            float wq = g_wsq[q];
#pragma unroll
            for (int i = 0; i < 4; i++) {
                float t1 = __fadd_rn(xsq[i], -__fmul_rn(2.0f, acc[i][j]));
                float d  = __fadd_rn(t1, wq);
                if (d < best[i]) { best[i] = d; bidx[i] = q; }
            }
        }
    }

    // Cross-thread (over tx) argmin per row, ties -> lowest index.
#pragma unroll
    for (int i = 0; i < 4; i++) {
        bestS[ty * 4 + i][tx] = best[i];
        idxS[ty * 4 + i][tx]  = bidx[i];
    }
    __syncthreads();

    if (t < TM) {
        float bb = 3.4e38f;
        int   bi = 0x7fffffff;
#pragma unroll
        for (int c = 0; c < 16; c++) {
            float v = bestS[t][c];
            int  ix = idxS[t][c];
            if (v < bb || (v == bb && ix < bi)) { bb = v; bi = ix; }
        }
        finalIdx[t] = bi;
        if (write_idx) out_idx[n0 + t] = (float)bi;
    }
    __syncthreads();

    // Gather winning codebook rows (float4; W rows are hot in L2).
    const float4* w4 = (const float4*)w;
    float4* o4 = (float4*)out;
#pragma unroll 4
    for (int i = t; i < TM * (E_DIM / 4); i += THREADS) {
        int r = i >> 7;
        int c = i & 127;
        o4[(size_t)(n0 + r) * (E_DIM / 4) + c] =
            w4[(size_t)finalIdx[r] * (E_DIM / 4) + c];
    }
}

// ---------------------------------------------------------------------------
extern "C" void kernel_launch(void* const* d_in, const int* in_sizes, int n_in,
                              void* d_out, int out_size)
{
    const float* x = (const float*)d_in[0];
    const float* w = (const float*)d_in[1];
    float* out = (float*)d_out;

    const int E = E_DIM;
    const int N = in_sizes[0] / E;   // 16384
    const int Q = in_sizes[1] / E;   // 8192

    const long long NE = (long long)N * E;
    int write_idx = (out_size >= NE + N) ? 1 : 0;
    float* out_idx = out + NE;

    rowsq_kernel<<<N / 128, 128>>>(x, N, 0);
    rowsq_kernel<<<Q / 128, 128>>>(w, Q, 1);
    vq_kernel<<<N / TM, THREADS>>>(x, w, out, out_idx, N, Q, write_idx);
}